// round 1
// baseline (speedup 1.0000x reference)
#include <cuda_runtime.h>
#include <math.h>
#include <stdint.h>

// Problem constants
#define BB   4
#define TT   2048
#define CC   1024
#define NH   16
#define DD   64
#define MROWS (BB*TT)          // 8192
#define OUT_ELEMS ((size_t)BB*TT*CC)   // 8388608

// Scratch (device globals — no allocation allowed)
__device__ float g_q[(size_t)BB*NH*TT*DD];
__device__ float g_k[(size_t)BB*NH*TT*DD];
__device__ float g_v[(size_t)BB*NH*TT*DD];
__device__ float g_attn[(size_t)MROWS*CC];

#define BIG_NEG (-3.0e38f)

// ---------------------------------------------------------------------------
// GEMM + bias: A (M x 1024) @ W (1024 x 1024) + bias
// mode 0/1/2: write q/k/v in (b,n,t,d) layout.  mode 3: A := g_attn, write
// plain row-major to out_plain.
// Block: 256 threads, 64x64 tile, 4x4 micro-tile.
// ---------------------------------------------------------------------------
__global__ __launch_bounds__(256) void gemm_bias_kernel(
    const float* __restrict__ A, const float* __restrict__ W,
    const float* __restrict__ bias, float* __restrict__ out_plain, int mode)
{
    __shared__ float Ast[16 * 65];   // transposed [k][row], pitch 65
    __shared__ float Bs[16 * 64];    // [k][col]

    const float* __restrict__ Ain = (mode == 3) ? g_attn : A;

    const int t  = threadIdx.x;
    const int tx = t & 15;
    const int ty = t >> 4;
    const int r0 = blockIdx.x * 64;
    const int c0 = blockIdx.y * 64;

    float acc[4][4] = {};

    for (int kk = 0; kk < CC; kk += 16) {
        // Load A tile (64x16) coalesced, store transposed
        {
            int row = t >> 2;            // 0..63
            int kq  = (t & 3) * 4;       // 0,4,8,12
            float4 av = *(const float4*)(Ain + (size_t)(r0 + row) * CC + kk + kq);
            Ast[(kq + 0) * 65 + row] = av.x;
            Ast[(kq + 1) * 65 + row] = av.y;
            Ast[(kq + 2) * 65 + row] = av.z;
            Ast[(kq + 3) * 65 + row] = av.w;
        }
        // Load W tile (16x64) coalesced
        {
            int kr = t >> 4;             // 0..15
            int cq = (t & 15) * 4;
            *(float4*)(Bs + kr * 64 + cq) =
                *(const float4*)(W + (size_t)(kk + kr) * 1024 + c0 + cq);
        }
        __syncthreads();

        #pragma unroll
        for (int k = 0; k < 16; k++) {
            float a[4];
            #pragma unroll
            for (int i = 0; i < 4; i++) a[i] = Ast[k * 65 + (ty << 2) + i];
            float4 b4 = *(const float4*)(Bs + (k << 6) + (tx << 2));
            float b[4] = {b4.x, b4.y, b4.z, b4.w};
            #pragma unroll
            for (int i = 0; i < 4; i++)
                #pragma unroll
                for (int j = 0; j < 4; j++)
                    acc[i][j] += a[i] * b[j];
        }
        __syncthreads();
    }

    // Bias + store
    float4 bv4 = *(const float4*)(bias + c0 + (tx << 2));
    float bv[4] = {bv4.x, bv4.y, bv4.z, bv4.w};

    #pragma unroll
    for (int i = 0; i < 4; i++) {
        int row = r0 + (ty << 2) + i;
        float4 o;
        o.x = acc[i][0] + bv[0];
        o.y = acc[i][1] + bv[1];
        o.z = acc[i][2] + bv[2];
        o.w = acc[i][3] + bv[3];
        if (mode < 3) {
            int b = row >> 11;           // row / 2048
            int tt = row & 2047;
            int n = blockIdx.y;          // one head per 64-col tile
            int d = tx << 2;
            float* dst = (mode == 0) ? g_q : (mode == 1) ? g_k : g_v;
            *(float4*)(dst + ((((size_t)b * NH + n) * TT + tt) << 6) + d) = o;
        } else {
            *(float4*)(out_plain + (size_t)row * 1024 + c0 + (tx << 2)) = o;
        }
    }
}

// ---------------------------------------------------------------------------
// Fused causal attention, 2-pass softmax with full-weights materialization.
// Grid: (T/64 q-blocks, B*N). Block: 256 threads, 64x64 tiles, 4x4 micro.
// Pass 1: online row max + sum (recompute scores per tile).
// Pass 2: recompute scores -> normalized weights -> write to gmem once,
//         accumulate O = W @ V in registers.  Upper tiles zero-filled.
// ---------------------------------------------------------------------------
__global__ __launch_bounds__(256) void attn_kernel(float* __restrict__ w_out,
                                                   int has_w)
{
    extern __shared__ float sm[];
    float* Qst  = sm;                  // transposed [d][r], pitch 68
    float* Kst  = Qst + 64 * 68;       // transposed [d][c], pitch 68
    float* Vs   = Kst + 64 * 68;       // row-major [c][d], pitch 68
    float* Ws   = Vs + 64 * 68;        // row-major [r][c], pitch 68
    float* mrow = Ws + 64 * 68;        // 64
    float* lrow = mrow + 64;           // 64

    const int t  = threadIdx.x;
    const int tx = t & 15;
    const int ty = t >> 4;
    const int qb = blockIdx.x;
    const int bn = blockIdx.y;
    const int q0 = qb * 64;

    const float* __restrict__ Qb = g_q + (size_t)bn * TT * DD;
    const float* __restrict__ Kb = g_k + (size_t)bn * TT * DD;
    const float* __restrict__ Vb = g_v + (size_t)bn * TT * DD;

    // Load Q tile transposed (once)
    #pragma unroll
    for (int uo = 0; uo < 4; uo++) {
        int idx = uo * 256 + t;
        int r = idx & 63;
        int dq = (idx >> 6) * 4;
        float4 v = *(const float4*)(Qb + (size_t)(q0 + r) * DD + dq);
        Qst[(dq + 0) * 68 + r] = v.x;
        Qst[(dq + 1) * 68 + r] = v.y;
        Qst[(dq + 2) * 68 + r] = v.z;
        Qst[(dq + 3) * 68 + r] = v.w;
    }
    if (t < 64) { mrow[t] = BIG_NEG; lrow[t] = 0.0f; }
    __syncthreads();

    // ---------------- PASS 1: row max + sum ----------------
    for (int kt = 0; kt <= qb; kt++) {
        #pragma unroll
        for (int uo = 0; uo < 4; uo++) {
            int idx = uo * 256 + t;
            int r = idx & 63;
            int dq = (idx >> 6) * 4;
            float4 v = *(const float4*)(Kb + (size_t)(kt * 64 + r) * DD + dq);
            Kst[(dq + 0) * 68 + r] = v.x;
            Kst[(dq + 1) * 68 + r] = v.y;
            Kst[(dq + 2) * 68 + r] = v.z;
            Kst[(dq + 3) * 68 + r] = v.w;
        }
        __syncthreads();

        float s[4][4] = {};
        #pragma unroll 16
        for (int d = 0; d < 64; d++) {
            float4 a4 = *(const float4*)(Qst + d * 68 + (ty << 2));
            float4 b4 = *(const float4*)(Kst + d * 68 + (tx << 2));
            float a[4] = {a4.x, a4.y, a4.z, a4.w};
            float b[4] = {b4.x, b4.y, b4.z, b4.w};
            #pragma unroll
            for (int i = 0; i < 4; i++)
                #pragma unroll
                for (int j = 0; j < 4; j++)
                    s[i][j] += a[i] * b[j];
        }
        const bool diag = (kt == qb);
        #pragma unroll
        for (int i = 0; i < 4; i++)
            #pragma unroll
            for (int j = 0; j < 4; j++) {
                s[i][j] *= 0.125f;
                if (diag && ((tx << 2) + j > (ty << 2) + i)) s[i][j] = BIG_NEG;
            }

        #pragma unroll
        for (int i = 0; i < 4; i++) {
            int r = (ty << 2) + i;
            float tm = fmaxf(fmaxf(s[i][0], s[i][1]), fmaxf(s[i][2], s[i][3]));
            #pragma unroll
            for (int off = 8; off > 0; off >>= 1)
                tm = fmaxf(tm, __shfl_xor_sync(0xffffffffu, tm, off, 16));
            float m_old = mrow[r];
            float m_new = fmaxf(m_old, tm);
            float ps = __expf(s[i][0] - m_new) + __expf(s[i][1] - m_new) +
                       __expf(s[i][2] - m_new) + __expf(s[i][3] - m_new);
            #pragma unroll
            for (int off = 8; off > 0; off >>= 1)
                ps += __shfl_xor_sync(0xffffffffu, ps, off, 16);
            float alpha = (m_old > -1.0e37f) ? __expf(m_old - m_new) : 0.0f;
            float l_new = lrow[r] * alpha + ps;
            if (tx == 0) { mrow[r] = m_new; lrow[r] = l_new; }
        }
        __syncthreads();
    }

    if (t < 64) lrow[t] = 1.0f / lrow[t];
    __syncthreads();

    // ---------------- PASS 2: weights + O accumulation ----------------
    float acc_o[4][4] = {};
    for (int kt = 0; kt <= qb; kt++) {
        #pragma unroll
        for (int uo = 0; uo < 4; uo++) {
            int idx = uo * 256 + t;
            int r = idx & 63;
            int dq = (idx >> 6) * 4;
            float4 v = *(const float4*)(Kb + (size_t)(kt * 64 + r) * DD + dq);
            Kst[(dq + 0) * 68 + r] = v.x;
            Kst[(dq + 1) * 68 + r] = v.y;
            Kst[(dq + 2) * 68 + r] = v.z;
            Kst[(dq + 3) * 68 + r] = v.w;
        }
        #pragma unroll
        for (int uo = 0; uo < 4; uo++) {
            int idx = uo * 256 + t;
            int c = idx >> 4;
            int dq = (idx & 15) * 4;
            *(float4*)(Vs + c * 68 + dq) =
                *(const float4*)(Vb + (size_t)(kt * 64 + c) * DD + dq);
        }
        __syncthreads();

        float s[4][4] = {};
        #pragma unroll 16
        for (int d = 0; d < 64; d++) {
            float4 a4 = *(const float4*)(Qst + d * 68 + (ty << 2));
            float4 b4 = *(const float4*)(Kst + d * 68 + (tx << 2));
            float a[4] = {a4.x, a4.y, a4.z, a4.w};
            float b[4] = {b4.x, b4.y, b4.z, b4.w};
            #pragma unroll
            for (int i = 0; i < 4; i++)
                #pragma unroll
                for (int j = 0; j < 4; j++)
                    s[i][j] += a[i] * b[j];
        }
        const bool diag = (kt == qb);
        #pragma unroll
        for (int i = 0; i < 4; i++) {
            int r = (ty << 2) + i;
            float m = mrow[r];
            float rl = lrow[r];
            float4 w;
            float sv[4];
            #pragma unroll
            for (int j = 0; j < 4; j++) {
                float x = s[i][j] * 0.125f;
                if (diag && ((tx << 2) + j > r)) x = BIG_NEG;
                sv[j] = __expf(x - m) * rl;
            }
            w.x = sv[0]; w.y = sv[1]; w.z = sv[2]; w.w = sv[3];
            *(float4*)(Ws + r * 68 + (tx << 2)) = w;
            if (has_w)
                *(float4*)(w_out + ((size_t)bn * TT + q0 + r) * TT + kt * 64 + (tx << 2)) = w;
        }
        __syncthreads();

        #pragma unroll 16
        for (int c = 0; c < 64; c++) {
            float4 b4 = *(const float4*)(Vs + c * 68 + (tx << 2));
            float b[4] = {b4.x, b4.y, b4.z, b4.w};
            float a[4];
            #pragma unroll
            for (int i = 0; i < 4; i++) a[i] = Ws[((ty << 2) + i) * 68 + c];
            #pragma unroll
            for (int i = 0; i < 4; i++)
                #pragma unroll
                for (int j = 0; j < 4; j++)
                    acc_o[i][j] += a[i] * b[j];
        }
        __syncthreads();
    }

    // Store O to attn scratch in (b, t, n*64+d) layout for the output GEMM
    {
        int b = bn >> 4;
        int n = bn & 15;
        #pragma unroll
        for (int i = 0; i < 4; i++) {
            int ig = q0 + (ty << 2) + i;
            float4 o;
            o.x = acc_o[i][0]; o.y = acc_o[i][1];
            o.z = acc_o[i][2]; o.w = acc_o[i][3];
            *(float4*)(g_attn + ((size_t)(b * TT + ig)) * CC + n * DD + (tx << 2)) = o;
        }
    }

    // Zero-fill strictly-upper tiles of the weights output
    if (has_w) {
        float4 z = {0.f, 0.f, 0.f, 0.f};
        for (int kt = qb + 1; kt < TT / 64; kt++) {
            #pragma unroll
            for (int i = 0; i < 4; i++) {
                int ig = q0 + (ty << 2) + i;
                *(float4*)(w_out + ((size_t)bn * TT + ig) * TT + kt * 64 + (tx << 2)) = z;
            }
        }
    }
}

// ---------------------------------------------------------------------------
extern "C" void kernel_launch(void* const* d_in, const int* in_sizes, int n_in,
                              void* d_out, int out_size)
{
    const float* x  = (const float*)d_in[0];
    const float* Wq = (const float*)d_in[1];
    const float* bq = (const float*)d_in[2];
    const float* Wk = (const float*)d_in[3];
    const float* bk = (const float*)d_in[4];
    const float* Wv = (const float*)d_in[5];
    const float* bv = (const float*)d_in[6];
    const float* Wo = (const float*)d_in[7];
    const float* bo = (const float*)d_in[8];
    float* out = (float*)d_out;

    int has_w = (out_size > (int)OUT_ELEMS) ? 1 : 0;
    float* w_out = has_w ? (out + OUT_ELEMS) : nullptr;

    const size_t attn_smem = (size_t)(4 * 64 * 68 + 128) * sizeof(float);
    cudaFuncSetAttribute(attn_kernel, cudaFuncAttributeMaxDynamicSharedMemorySize,
                         (int)attn_smem);

    dim3 gblk(256);
    dim3 ggrid(MROWS / 64, CC / 64);

    gemm_bias_kernel<<<ggrid, gblk>>>(x, Wq, bq, nullptr, 0);
    gemm_bias_kernel<<<ggrid, gblk>>>(x, Wk, bk, nullptr, 1);
    gemm_bias_kernel<<<ggrid, gblk>>>(x, Wv, bv, nullptr, 2);

    dim3 agrid(TT / 64, BB * NH);
    attn_kernel<<<agrid, gblk, attn_smem>>>(w_out, has_w);

    gemm_bias_kernel<<<ggrid, gblk>>>(nullptr, Wo, bo, out, 3);
}

// round 2
// speedup vs baseline: 2.9550x; 2.9550x over previous
#include <cuda_runtime.h>
#include <math.h>
#include <stdint.h>

// Problem constants
#define BB   4
#define TT   2048
#define CC   1024
#define NH   16
#define DD   64
#define MROWS (BB*TT)                      // 8192
#define OUT_ELEMS ((size_t)BB*TT*CC)       // 8388608

// Scratch (device globals — no allocation allowed)
__device__ float g_x[(size_t)MROWS*CC];            // tf32-rounded x
__device__ float g_wt[4*(size_t)CC*CC];            // W^T, tf32-rounded (q,k,v,o)
__device__ float g_q[(size_t)BB*NH*TT*DD];         // [bn][t][d]
__device__ float g_k[(size_t)BB*NH*TT*DD];         // [bn][t][d]
__device__ float g_v[(size_t)BB*NH*TT*DD];         // [bn][d][t]  (transposed)
__device__ float g_attn[(size_t)MROWS*CC];         // [b][t][n*64+d]
__device__ float g_linv[(size_t)BB*NH*TT];         // 1/rowsum

// ---------------------------------------------------------------------------
// PTX helpers
// ---------------------------------------------------------------------------
__device__ __forceinline__ uint32_t smem_u32(const void* p) {
    return (uint32_t)__cvta_generic_to_shared(p);
}
__device__ __forceinline__ float tf32r(float x) {
    uint32_t u;
    asm("cvt.rna.tf32.f32 %0, %1;" : "=r"(u) : "f"(x));
    return __uint_as_float(u);
}
__device__ __forceinline__ void ldsm4(uint32_t a, uint32_t& r0, uint32_t& r1,
                                      uint32_t& r2, uint32_t& r3) {
    asm volatile("ldmatrix.sync.aligned.m8n8.x4.shared.b16 {%0,%1,%2,%3}, [%4];"
                 : "=r"(r0), "=r"(r1), "=r"(r2), "=r"(r3) : "r"(a));
}
__device__ __forceinline__ void ldsm2(uint32_t a, uint32_t& r0, uint32_t& r1) {
    asm volatile("ldmatrix.sync.aligned.m8n8.x2.shared.b16 {%0,%1}, [%2];"
                 : "=r"(r0), "=r"(r1) : "r"(a));
}
__device__ __forceinline__ void mma_tf32(float& c0, float& c1, float& c2, float& c3,
                                         uint32_t a0, uint32_t a1, uint32_t a2, uint32_t a3,
                                         uint32_t b0, uint32_t b1) {
    asm volatile(
        "mma.sync.aligned.m16n8k8.row.col.f32.tf32.tf32.f32 "
        "{%0,%1,%2,%3}, {%4,%5,%6,%7}, {%8,%9}, {%0,%1,%2,%3};"
        : "+f"(c0), "+f"(c1), "+f"(c2), "+f"(c3)
        : "r"(a0), "r"(a1), "r"(a2), "r"(a3), "r"(b0), "r"(b1));
}
__device__ __forceinline__ void cpasync16(uint32_t saddr, const void* g) {
    asm volatile("cp.async.cg.shared.global [%0], [%1], 16;" :: "r"(saddr), "l"(g));
}
#define CP_COMMIT asm volatile("cp.async.commit_group;")
#define CP_WAIT1  asm volatile("cp.async.wait_group 1;")
#define CP_WAIT0  asm volatile("cp.async.wait_group 0;")

// ---------------------------------------------------------------------------
// Pre-pass: round x to tf32
// ---------------------------------------------------------------------------
__global__ __launch_bounds__(256) void round_x_kernel(const float* __restrict__ x)
{
    size_t i = ((size_t)blockIdx.x * 256 + threadIdx.x) * 4;
    float4 v = *(const float4*)(x + i);
    v.x = tf32r(v.x); v.y = tf32r(v.y); v.z = tf32r(v.z); v.w = tf32r(v.w);
    *(float4*)(g_x + i) = v;
}

// Pre-pass: transpose + round W (1024x1024) into g_wt[which]
__global__ __launch_bounds__(256) void transpose_w_kernel(const float* __restrict__ W,
                                                          int which)
{
    __shared__ float tile[32][33];
    int bx = blockIdx.x * 32, by = blockIdx.y * 32;
    int tx = threadIdx.x & 31, ty = threadIdx.x >> 5;   // 32 x 8
    #pragma unroll
    for (int i = 0; i < 4; i++)
        tile[ty + 8 * i][tx] = W[(size_t)(by + ty + 8 * i) * CC + bx + tx];
    __syncthreads();
    float* dst = g_wt + (size_t)which * CC * CC;
    #pragma unroll
    for (int i = 0; i < 4; i++)
        dst[(size_t)(bx + ty + 8 * i) * CC + by + tx] = tf32r(tile[tx][ty + 8 * i]);
}

// ---------------------------------------------------------------------------
// tf32 GEMM: C(M x 1024) = A(M x 1024) @ W, A row-major, W^T in g_wt[w_sel].
// CTA 256 thr, tile 128x128, warp tile 64x32, k-stage 32, cp.async dbl-buffer.
// mode 0/1: Q/K -> [bn][t][d] (tf32-rounded). mode 2: V -> [bn][d][t] rounded.
// mode 3: final out (plain fp32).
// ---------------------------------------------------------------------------
#define GP 44
#define GEMM_SMEM (4 * 128 * GP * 4)

__global__ __launch_bounds__(256) void gemm_tf32(int a_sel, int w_sel,
                                                 const float* __restrict__ bias,
                                                 float* __restrict__ dst_ext, int mode)
{
    extern __shared__ float sm[];
    float* As = sm;                       // [2][128*GP]
    float* Bs = sm + 2 * 128 * GP;        // [2][128*GP]

    const float* __restrict__ A  = a_sel ? g_attn : g_x;
    const float* __restrict__ BT = g_wt + (size_t)w_sel * CC * CC;

    const int t = threadIdx.x, lane = t & 31, warp = t >> 5;
    const int wm = (warp >> 2) * 64, wn = (warp & 3) * 32;
    const int bm = blockIdx.x * 128, bnc = blockIdx.y * 128;

    const uint32_t sA = smem_u32(As), sB = smem_u32(Bs);

    float acc[4][4][4] = {};

    // stage loader
    auto load_stage = [&](int ks, int buf) {
        int k0 = ks * 32;
        #pragma unroll
        for (int i = 0; i < 4; i++) {
            int lin = t + 256 * i;
            int row = lin >> 3;
            int c4  = (lin & 7) << 2;
            uint32_t so = (uint32_t)((buf * 128 * GP + row * GP + c4) << 2);
            cpasync16(sA + so, A  + (size_t)(bm + row) * CC + k0 + c4);
            cpasync16(sB + so, BT + (size_t)(bnc + row) * CC + k0 + c4);
        }
        CP_COMMIT;
    };

    load_stage(0, 0);
    for (int ks = 0; ks < 32; ks++) {
        int buf = ks & 1;
        if (ks + 1 < 32) { load_stage(ks + 1, (ks + 1) & 1); CP_WAIT1; }
        else             { CP_WAIT0; }
        __syncthreads();

        #pragma unroll
        for (int kk = 0; kk < 4; kk++) {
            uint32_t af[4][4];
            #pragma unroll
            for (int mt = 0; mt < 4; mt++) {
                uint32_t a = sA + (uint32_t)((buf * 128 * GP +
                              (wm + mt * 16 + (lane & 15)) * GP +
                              kk * 8 + ((lane >> 4) << 2)) << 2);
                ldsm4(a, af[mt][0], af[mt][1], af[mt][2], af[mt][3]);
            }
            #pragma unroll
            for (int nt = 0; nt < 4; nt++) {
                uint32_t b0, b1;
                uint32_t a = sB + (uint32_t)((buf * 128 * GP +
                              (wn + nt * 8 + (lane & 7)) * GP +
                              kk * 8 + (((lane >> 3) & 1) << 2)) << 2);
                ldsm2(a, b0, b1);
                #pragma unroll
                for (int mt = 0; mt < 4; mt++)
                    mma_tf32(acc[mt][nt][0], acc[mt][nt][1], acc[mt][nt][2], acc[mt][nt][3],
                             af[mt][0], af[mt][1], af[mt][2], af[mt][3], b0, b1);
            }
        }
        __syncthreads();
    }

    // Epilogue
    #pragma unroll
    for (int mt = 0; mt < 4; mt++) {
        #pragma unroll
        for (int nt = 0; nt < 4; nt++) {
            int r = bm + wm + mt * 16 + (lane >> 2);
            int c = bnc + wn + nt * 8 + ((lane & 3) << 1);
            float bv0 = bias[c], bv1 = bias[c + 1];
            float v0 = acc[mt][nt][0] + bv0, v1 = acc[mt][nt][1] + bv1;
            float v2 = acc[mt][nt][2] + bv0, v3 = acc[mt][nt][3] + bv1;
            if (mode == 3) {
                *(float2*)(dst_ext + (size_t)r * CC + c)       = make_float2(v0, v1);
                *(float2*)(dst_ext + (size_t)(r + 8) * CC + c) = make_float2(v2, v3);
            } else {
                int b = r >> 11, tt = r & 2047;
                int hn = c >> 6, d = c & 63;
                size_t bnix = (size_t)(b * NH + hn);
                if (mode == 2) {
                    g_v[(bnix * DD + d)     * TT + tt]     = tf32r(v0);
                    g_v[(bnix * DD + d + 1) * TT + tt]     = tf32r(v1);
                    g_v[(bnix * DD + d)     * TT + tt + 8] = tf32r(v2);
                    g_v[(bnix * DD + d + 1) * TT + tt + 8] = tf32r(v3);
                } else {
                    float* dst = (mode == 0) ? g_q : g_k;
                    *(float2*)(dst + (bnix * TT + tt) * DD + d) =
                        make_float2(tf32r(v0), tf32r(v1));
                    *(float2*)(dst + (bnix * TT + tt + 8) * DD + d) =
                        make_float2(tf32r(v2), tf32r(v3));
                }
            }
        }
    }
}

// ---------------------------------------------------------------------------
// Single-pass causal attention (tf32 mma). Writes UNNORMALIZED exp weights to
// w_out, 1/rowsum to g_linv, normalized O (tf32-rounded) to g_attn.
// Grid (32 qtiles reversed, 64 bn), block 128 (4 warps x 16 q-rows).
// ---------------------------------------------------------------------------
#define AP 68
#define ATTN_SMEM (3 * 64 * AP * 4)

__global__ __launch_bounds__(128) void attn_tf32(float* __restrict__ w_out)
{
    extern __shared__ float sm[];
    float* Qs = sm;               // [64][AP]  (reused as P stage)
    float* Ks = sm + 64 * AP;     // [64][AP]  [tok][d]
    float* Vs = Ks + 64 * AP;     // [64][AP]  [d][tok]

    const int t = threadIdx.x, lane = t & 31, wid = t >> 5;
    const int qb = gridDim.x - 1 - blockIdx.x;   // longest blocks first
    const int bn = blockIdx.y;
    const int q0 = qb * 64;

    const float* __restrict__ Qg = g_q + (size_t)bn * TT * DD;
    const float* __restrict__ Kg = g_k + (size_t)bn * TT * DD;
    const float* __restrict__ Vg = g_v + (size_t)bn * DD * TT;

    // Load Q tile [64][64]
    #pragma unroll
    for (int i = 0; i < 8; i++) {
        int lin = t + 128 * i;
        int row = lin >> 4;
        int c4  = (lin & 15) << 2;
        *(float4*)(Qs + row * AP + c4) = *(const float4*)(Qg + (size_t)(q0 + row) * DD + c4);
    }
    __syncthreads();

    const uint32_t sQ = smem_u32(Qs), sK = smem_u32(Ks), sV = smem_u32(Vs);

    // Q fragments (persistent): 8 d-steps x 4 regs
    uint32_t qf[8][4];
    #pragma unroll
    for (int ds = 0; ds < 8; ds++) {
        uint32_t a = sQ + (uint32_t)(((wid * 16 + (lane & 15)) * AP +
                          ds * 8 + ((lane >> 4) << 2)) << 2);
        ldsm4(a, qf[ds][0], qf[ds][1], qf[ds][2], qf[ds][3]);
    }

    float o[8][4] = {};
    float l0 = 0.f, l1 = 0.f;
    const int rl = lane >> 2;
    const int cl = (lane & 3) << 1;
    const int rowg0 = q0 + wid * 16 + rl;
    const int rowg1 = rowg0 + 8;
    float* wrow0 = w_out + ((size_t)bn * TT + rowg0) * TT;
    float* wrow1 = w_out + ((size_t)bn * TT + rowg1) * TT;

    for (int kt = 0; kt <= qb; kt++) {
        __syncthreads();
        #pragma unroll
        for (int i = 0; i < 8; i++) {
            int lin = t + 128 * i;
            int row = lin >> 4;
            int c4  = (lin & 15) << 2;
            *(float4*)(Ks + row * AP + c4) =
                *(const float4*)(Kg + (size_t)(kt * 64 + row) * DD + c4);
            *(float4*)(Vs + row * AP + c4) =
                *(const float4*)(Vg + (size_t)row * TT + kt * 64 + c4);
        }
        __syncthreads();

        // ---- scores + softmax numerator + staging ----
        #pragma unroll
        for (int nt = 0; nt < 8; nt++) {
            float s0 = 0.f, s1 = 0.f, s2 = 0.f, s3 = 0.f;
            #pragma unroll
            for (int dp = 0; dp < 4; dp++) {
                uint32_t b00, b01, b10, b11;
                uint32_t a = sK + (uint32_t)(((nt * 8 + (lane & 7)) * AP +
                                  dp * 16 + ((lane >> 3) << 2)) << 2);
                ldsm4(a, b00, b01, b10, b11);
                mma_tf32(s0, s1, s2, s3, qf[2*dp][0], qf[2*dp][1], qf[2*dp][2], qf[2*dp][3], b00, b01);
                mma_tf32(s0, s1, s2, s3, qf[2*dp+1][0], qf[2*dp+1][1], qf[2*dp+1][2], qf[2*dp+1][3], b10, b11);
            }
            int colg = kt * 64 + nt * 8 + cl;
            float p0 = __expf(s0 * 0.125f);
            float p1 = __expf(s1 * 0.125f);
            float p2 = __expf(s2 * 0.125f);
            float p3 = __expf(s3 * 0.125f);
            if (kt == qb) {
                if (colg     > rowg0) p0 = 0.f;
                if (colg + 1 > rowg0) p1 = 0.f;
                if (colg     > rowg1) p2 = 0.f;
                if (colg + 1 > rowg1) p3 = 0.f;
            }
            p0 = tf32r(p0); p1 = tf32r(p1); p2 = tf32r(p2); p3 = tf32r(p3);
            l0 += p0 + p1;
            l1 += p2 + p3;
            *(float2*)(wrow0 + colg) = make_float2(p0, p1);
            *(float2*)(wrow1 + colg) = make_float2(p2, p3);
            int lr = wid * 16 + rl, lc = nt * 8 + cl;
            *(float2*)(Qs + lr * AP + lc)       = make_float2(p0, p1);
            *(float2*)(Qs + (lr + 8) * AP + lc) = make_float2(p2, p3);
        }
        __syncwarp();

        // ---- P fragments ----
        uint32_t pf[8][4];
        #pragma unroll
        for (int ksx = 0; ksx < 8; ksx++) {
            uint32_t a = sQ + (uint32_t)(((wid * 16 + (lane & 15)) * AP +
                              ksx * 8 + ((lane >> 4) << 2)) << 2);
            ldsm4(a, pf[ksx][0], pf[ksx][1], pf[ksx][2], pf[ksx][3]);
        }
        // ---- O += P @ V ----
        #pragma unroll
        for (int nt = 0; nt < 8; nt++) {
            #pragma unroll
            for (int kp = 0; kp < 4; kp++) {
                uint32_t b00, b01, b10, b11;
                uint32_t a = sV + (uint32_t)(((nt * 8 + (lane & 7)) * AP +
                                  kp * 16 + ((lane >> 3) << 2)) << 2);
                ldsm4(a, b00, b01, b10, b11);
                mma_tf32(o[nt][0], o[nt][1], o[nt][2], o[nt][3],
                         pf[2*kp][0], pf[2*kp][1], pf[2*kp][2], pf[2*kp][3], b00, b01);
                mma_tf32(o[nt][0], o[nt][1], o[nt][2], o[nt][3],
                         pf[2*kp+1][0], pf[2*kp+1][1], pf[2*kp+1][2], pf[2*kp+1][3], b10, b11);
            }
        }
    }

    // row sums -> 1/l
    l0 += __shfl_xor_sync(0xffffffffu, l0, 1);
    l0 += __shfl_xor_sync(0xffffffffu, l0, 2);
    l1 += __shfl_xor_sync(0xffffffffu, l1, 1);
    l1 += __shfl_xor_sync(0xffffffffu, l1, 2);
    float li0 = 1.f / l0, li1 = 1.f / l1;

    // store O (normalized, tf32-rounded) in [b][t][hn*64+d]
    int b = bn >> 4, hn = bn & 15;
    float* Og0 = g_attn + ((size_t)b * TT + rowg0) * CC + hn * DD;
    float* Og1 = g_attn + ((size_t)b * TT + rowg1) * CC + hn * DD;
    #pragma unroll
    for (int nt = 0; nt < 8; nt++) {
        *(float2*)(Og0 + nt * 8 + cl) =
            make_float2(tf32r(o[nt][0] * li0), tf32r(o[nt][1] * li0));
        *(float2*)(Og1 + nt * 8 + cl) =
            make_float2(tf32r(o[nt][2] * li1), tf32r(o[nt][3] * li1));
    }
    if ((lane & 3) == 0) {
        g_linv[(size_t)bn * TT + rowg0] = li0;
        g_linv[(size_t)bn * TT + rowg1] = li1;
    }
}

// ---------------------------------------------------------------------------
// Normalize weights rows + zero-fill upper triangle.  One block per row.
// ---------------------------------------------------------------------------
__global__ __launch_bounds__(256) void scale_w_kernel(float* __restrict__ w)
{
    int R = blockIdx.x;                  // 0 .. 64*2048-1
    int q = R & 2047;
    float li = g_linv[R];
    float* row = w + (size_t)R * TT;
    #pragma unroll
    for (int i = 0; i < 2; i++) {
        int c4  = threadIdx.x + (i << 8);
        int col = c4 << 2;
        float4 v;
        if (col <= q) {
            v = *(float4*)(row + col);
            v.x = v.x * li;
            v.y = (col + 1 <= q) ? v.y * li : 0.f;
            v.z = (col + 2 <= q) ? v.z * li : 0.f;
            v.w = (col + 3 <= q) ? v.w * li : 0.f;
        } else {
            v = make_float4(0.f, 0.f, 0.f, 0.f);
        }
        *(float4*)(row + col) = v;
    }
}

// ---------------------------------------------------------------------------
extern "C" void kernel_launch(void* const* d_in, const int* in_sizes, int n_in,
                              void* d_out, int out_size)
{
    const float* x  = (const float*)d_in[0];
    const float* Wq = (const float*)d_in[1];
    const float* bq = (const float*)d_in[2];
    const float* Wk = (const float*)d_in[3];
    const float* bk = (const float*)d_in[4];
    const float* Wv = (const float*)d_in[5];
    const float* bv = (const float*)d_in[6];
    const float* Wo = (const float*)d_in[7];
    const float* bo = (const float*)d_in[8];
    float* out = (float*)d_out;
    float* w_out = out + OUT_ELEMS;

    cudaFuncSetAttribute(gemm_tf32, cudaFuncAttributeMaxDynamicSharedMemorySize, GEMM_SMEM);
    cudaFuncSetAttribute(attn_tf32, cudaFuncAttributeMaxDynamicSharedMemorySize, ATTN_SMEM);

    // Pre-round / transpose
    round_x_kernel<<<(MROWS * CC) / (256 * 4), 256>>>(x);
    dim3 tg(32, 32);
    transpose_w_kernel<<<tg, 256>>>(Wq, 0);
    transpose_w_kernel<<<tg, 256>>>(Wk, 1);
    transpose_w_kernel<<<tg, 256>>>(Wv, 2);
    transpose_w_kernel<<<tg, 256>>>(Wo, 3);

    dim3 gg(MROWS / 128, CC / 128);
    gemm_tf32<<<gg, 256, GEMM_SMEM>>>(0, 0, bq, nullptr, 0);
    gemm_tf32<<<gg, 256, GEMM_SMEM>>>(0, 1, bk, nullptr, 1);
    gemm_tf32<<<gg, 256, GEMM_SMEM>>>(0, 2, bv, nullptr, 2);

    dim3 ag(TT / 64, BB * NH);
    attn_tf32<<<ag, 128, ATTN_SMEM>>>(w_out);

    gemm_tf32<<<gg, 256, GEMM_SMEM>>>(1, 3, bo, out, 3);

    scale_w_kernel<<<BB * NH * TT, 256>>>(w_out);
}